// round 12
// baseline (speedup 1.0000x reference)
#include <cuda_runtime.h>

// ---------------------------------------------------------------------------
// 2-level 3D inverse DWT (db4, mode='zero').
// Structure: per level, z streaming pass (8->4 bands) then fused y+x (4->1).
// Level 2 is chunked over slices (4 chunks x 4 slices) with ping-pong 35 MB
// scratch buffers so the intermediate stays L2-resident, and each launch
// CO-SCHEDULES chunk c's y/x-pass with chunk c+1's z-pass (independent
// buffers) in one kernel via block partitioning -> serialization loss of
// R10-style chunking is recovered while keeping the DRAM saving.
//
// Synthesis (L=8, conv_transpose stride 2, pad 6): out len M = 2n-6,
//   y[2p]   = sum_t x[p+t]*g[6-2t],  y[2p+1] = sum_t x[p+t]*g[7-2t]
// ---------------------------------------------------------------------------

#define G0_0 0.23037781330885523f
#define G0_1 0.7148465705525415f
#define G0_2 0.6308807679295904f
#define G0_3 (-0.02798376941698385f)
#define G0_4 (-0.18703481171888114f)
#define G0_5 0.030841381835986965f
#define G0_6 0.032883011666982945f
#define G0_7 (-0.010597401784997278f)

#define G1_0 (-0.010597401784997278f)
#define G1_1 (-0.032883011666982945f)
#define G1_2 0.030841381835986965f
#define G1_3 0.18703481171888114f
#define G1_4 (-0.02798376941698385f)
#define G1_5 (-0.6308807679295904f)
#define G1_6 0.7148465705525415f
#define G1_7 (-0.23037781330885523f)

__device__ __forceinline__ void sfb_pair(
    float l0, float l1, float l2, float l3,
    float h0, float h1, float h2, float h3,
    float& ye, float& yo)
{
    ye = fmaf(l0, G0_6,
         fmaf(l1, G0_4,
         fmaf(l2, G0_2,
         fmaf(l3, G0_0,
         fmaf(h0, G1_6,
         fmaf(h1, G1_4,
         fmaf(h2, G1_2,
              h3 * G1_0)))))));
    yo = fmaf(l0, G0_7,
         fmaf(l1, G0_5,
         fmaf(l2, G0_3,
         fmaf(l3, G0_1,
         fmaf(h0, G1_7,
         fmaf(h1, G1_5,
         fmaf(h2, G1_3,
              h3 * G1_1)))))));
}

__device__ __forceinline__ void sfb_pair2(
    float2 l0, float2 l1, float2 l2, float2 l3,
    float2 h0, float2 h1, float2 h2, float2 h3,
    float2& ye, float2& yo)
{
    sfb_pair(l0.x, l1.x, l2.x, l3.x, h0.x, h1.x, h2.x, h3.x, ye.x, yo.x);
    sfb_pair(l0.y, l1.y, l2.y, l3.y, h0.y, h1.y, h2.y, h3.y, ye.y, yo.y);
}

__device__ __forceinline__ void sfb_pair4(
    float4 l0, float4 l1, float4 l2, float4 l3,
    float4 h0, float4 h1, float4 h2, float4 h3,
    float4& ye, float4& yo)
{
    sfb_pair(l0.x, l1.x, l2.x, l3.x, h0.x, h1.x, h2.x, h3.x, ye.x, yo.x);
    sfb_pair(l0.y, l1.y, l2.y, l3.y, h0.y, h1.y, h2.y, h3.y, ye.y, yo.y);
    sfb_pair(l0.z, l1.z, l2.z, l3.z, h0.z, h1.z, h2.z, h3.z, ye.z, yo.z);
    sfb_pair(l0.w, l1.w, l2.w, l3.w, h0.w, h1.w, h2.w, h3.w, ye.w, yo.w);
}

// Ping-pong chunk scratch: 4 slices * 4 bands * 126 * 66^2 = 8,781,696 floats
// (35.1 MB) each. Level-1 MID (21.9 MB) reuses buffer A.
__device__ float g_midA[8781696];
__device__ float g_midB[8781696];
__device__ float g_LL1[4599936];    // 16 * 66^3 (18.4 MB)

#define TPB 256

// ---------------------------------------------------------------------------
// z synthesis bodies. Thread = (segment of PP pairs, vector column), g = local
// slice*4 + b4. NSEG*PP = N-3. Output layout: [g][M_z][N^2].
// ---------------------------------------------------------------------------
template<int N, int PP>
__device__ __forceinline__ void zpass4_dev(int item, int g,
                                           const float* __restrict__ lo_t,
                                           const float* __restrict__ yh,
                                           float* __restrict__ out)
{
    constexpr int N2 = N * N, M = 2 * N - 6, S = N2 / 4, VOL = N2 * N;
    int i4  = item % S;
    int seg = item / S;
    int p0  = seg * PP;
    int slice = g >> 2, b4 = g & 3;

    const float* lo_s = (b4 == 0) ? lo_t + slice * VOL
                                  : yh + (slice * 7 + (b4 - 1)) * VOL;
    const float* hi_s = yh + (slice * 7 + (b4 + 3)) * VOL;

    const float4* lp = (const float4*)lo_s + i4 + p0 * S;
    const float4* hp = (const float4*)hi_s + i4 + p0 * S;
    float4* op = (float4*)(out + g * M * N2) + i4 + 2 * p0 * S;

    float4 l0 = lp[0], l1 = lp[S], l2 = lp[2 * S];
    float4 h0 = hp[0], h1 = hp[S], h2 = hp[2 * S];
    lp += 3 * S; hp += 3 * S;

    #pragma unroll
    for (int p = 0; p < PP; p++) {
        float4 l3 = *lp, h3 = *hp;
        float4 ye, yo;
        sfb_pair4(l0, l1, l2, l3, h0, h1, h2, h3, ye, yo);
        op[0] = ye;
        op[S] = yo;
        l0 = l1; l1 = l2; l2 = l3;
        h0 = h1; h1 = h2; h2 = h3;
        lp += S; hp += S; op += 2 * S;
    }
}

// float2 variant (lower register pressure, 2x threads) for the pipe kernel.
template<int N, int PP>
__device__ __forceinline__ void zpass2_dev(int item, int g,
                                           const float* __restrict__ lo_t,
                                           const float* __restrict__ yh,
                                           float* __restrict__ out)
{
    constexpr int N2 = N * N, M = 2 * N - 6, S = N2 / 2, VOL = N2 * N;
    int i2  = item % S;
    int seg = item / S;
    int p0  = seg * PP;
    int slice = g >> 2, b4 = g & 3;

    const float* lo_s = (b4 == 0) ? lo_t + slice * VOL
                                  : yh + (slice * 7 + (b4 - 1)) * VOL;
    const float* hi_s = yh + (slice * 7 + (b4 + 3)) * VOL;

    const float2* lp = (const float2*)lo_s + i2 + p0 * S;
    const float2* hp = (const float2*)hi_s + i2 + p0 * S;
    float2* op = (float2*)(out + g * M * N2) + i2 + 2 * p0 * S;

    float2 l0 = lp[0], l1 = lp[S], l2 = lp[2 * S];
    float2 h0 = hp[0], h1 = hp[S], h2 = hp[2 * S];
    lp += 3 * S; hp += 3 * S;

    #pragma unroll
    for (int p = 0; p < PP; p++) {
        float2 l3 = *lp, h3 = *hp;
        float2 ye, yo;
        sfb_pair2(l0, l1, l2, l3, h0, h1, h2, h3, ye, yo);
        op[0] = ye;
        op[S] = yo;
        l0 = l1; l1 = l2; l2 = l3;
        h0 = h1; h1 = h2; h2 = h3;
        lp += S; hp += S; op += 2 * S;
    }
}

// ---------------------------------------------------------------------------
// Fused y + x synthesis body (R9-proven). 4 bands -> 1. Requires TY | (N-3).
//   smem: s_in [4][TY+3][N], s_mid [2][2*TY][N]
// ---------------------------------------------------------------------------
template<int N, int TY, int NQ, int NCH>
__device__ __forceinline__ void kyx_dev(float* sm, int tid,
                                        int tilex, int oz, int slice,
                                        const float* __restrict__ in,
                                        float* __restrict__ outp)
{
    constexpr int N2   = N * N;
    constexpr int M    = 2 * N - 6;
    constexpr int NH   = N / 2;
    constexpr int WINY = TY + 3;
    constexpr int ROWS = 2 * TY;
    constexpr int MN2  = M * N2;
    constexpr int MVOL = M * M * M;

    float* s_in  = sm;                  // [4][WINY][N]
    float* s_mid = sm + 4 * WINY * N;   // [2][ROWS][N]
    const int py0 = tilex * TY;

    // ---- load 4 bands x WINY rows x N floats (float2, coalesced) ----
    {
        const float* base = in + (slice * 4 * M + oz) * N2 + py0 * N;
        constexpr int NLOAD = 4 * WINY * NH;
        constexpr int KL = (NLOAD + TPB - 1) / TPB;
        #pragma unroll
        for (int k = 0; k < KL; k++) {
            int idx = tid + k * TPB;
            if (KL * TPB == NLOAD || idx < NLOAD) {
                int b  = idx / (WINY * NH);
                int r  = idx - b * (WINY * NH);
                int iy = r / NH;
                int x2 = r - iy * NH;
                float2 v = *(const float2*)(base + b * MN2 + iy * N + 2 * x2);
                *(float2*)(s_in + (b * WINY + iy) * N + 2 * x2) = v;
            }
        }
    }
    __syncthreads();

    // ---- y synthesis: bands (j, j+2) -> s_mid[j]; chunk of 3 pairs ----
    {
        constexpr int YIT = 2 * NQ * NH;
        constexpr int KY = (YIT + TPB - 1) / TPB;
        #pragma unroll
        for (int k = 0; k < KY; k++) {
            int idx = tid + k * TPB;
            if (KY * TPB == YIT || idx < YIT) {
                int x2 = idx % NH;
                int rr = idx / NH;
                int q  = rr % NQ;
                int j  = rr / NQ;
                int p0 = 3 * q;
                const float* lp = s_in + (j * WINY + p0) * N + 2 * x2;
                const float* hp = lp + 2 * WINY * N;
                float2 l0 = *(const float2*)(lp);
                float2 l1 = *(const float2*)(lp + N);
                float2 l2 = *(const float2*)(lp + 2 * N);
                float2 l3 = *(const float2*)(lp + 3 * N);
                float2 h0 = *(const float2*)(hp);
                float2 h1 = *(const float2*)(hp + N);
                float2 h2 = *(const float2*)(hp + 2 * N);
                float2 h3 = *(const float2*)(hp + 3 * N);
                float* op = s_mid + (j * ROWS + 2 * p0) * N + 2 * x2;
                float2 ye, yo;
                sfb_pair2(l0, l1, l2, l3, h0, h1, h2, h3, ye, yo);
                *(float2*)(op)     = ye;
                *(float2*)(op + N) = yo;
                if (p0 + 1 < TY) {
                    float2 l4 = *(const float2*)(lp + 4 * N);
                    float2 h4 = *(const float2*)(hp + 4 * N);
                    sfb_pair2(l1, l2, l3, l4, h1, h2, h3, h4, ye, yo);
                    *(float2*)(op + 2 * N) = ye;
                    *(float2*)(op + 3 * N) = yo;
                    if (p0 + 2 < TY) {
                        float2 l5 = *(const float2*)(lp + 5 * N);
                        float2 h5 = *(const float2*)(hp + 5 * N);
                        sfb_pair2(l2, l3, l4, l5, h2, h3, h4, h5, ye, yo);
                        *(float2*)(op + 4 * N) = ye;
                        *(float2*)(op + 5 * N) = yo;
                    }
                }
            }
        }
    }
    __syncthreads();

    // ---- x synthesis: item = (row, chunk of 3 pairs), rolling, to global ----
    {
        constexpr int XIT = ROWS * NCH;
        constexpr int KX = (XIT + TPB - 1) / TPB;
        float* oslab = outp + slice * MVOL + (oz * M + 2 * py0) * M;
        #pragma unroll
        for (int k = 0; k < KX; k++) {
            int idx = tid + k * TPB;
            if (KX * TPB == XIT || idx < XIT) {
                int c   = idx % NCH;
                int row = idx / NCH;
                int p0  = 3 * c;
                const float* lp = s_mid + row * N + p0;
                const float* hp = lp + ROWS * N;
                float l0 = lp[0], l1 = lp[1], l2 = lp[2];
                float h0 = hp[0], h1 = hp[1], h2 = hp[2];
                float* o = oslab + row * M + 2 * p0;
                #pragma unroll
                for (int s = 0; s < 3; s++) {
                    float l3 = lp[3 + s], h3 = hp[3 + s];
                    float ye, yo;
                    sfb_pair(l0, l1, l2, l3, h0, h1, h2, h3, ye, yo);
                    *(float2*)(o + 2 * s) = make_float2(ye, yo);
                    l0 = l1; l1 = l2; l2 = l3;
                    h0 = h1; h1 = h2; h2 = h3;
                }
            }
        }
    }
}

// ---------------------------------------------------------------------------
// Level-1 standalone kernels
// ---------------------------------------------------------------------------
template<int N, int NSEG, int PP>
__global__ void k_zpass(const float* __restrict__ lo,
                        const float* __restrict__ yh,
                        float* __restrict__ out)
{
    constexpr int ITEMS = (N * N / 4) * NSEG;
    int idx = blockIdx.x * blockDim.x + threadIdx.x;
    if (idx >= ITEMS) return;
    zpass4_dev<N, PP>(idx, blockIdx.y, lo, yh, out);
}

template<int N, int TY, int NQ, int NCH>
__global__ void k_yx(const float* __restrict__ in, float* __restrict__ out)
{
    extern __shared__ float sm[];
    kyx_dev<N, TY, NQ, NCH>(sm, threadIdx.x, blockIdx.x, blockIdx.y, blockIdx.z,
                            in, out);
}

// ---------------------------------------------------------------------------
// Level-2 pipelined kernel: blocks [0, nzblk) run the z-pass of the NEXT chunk
// (float2 body, -> midw); remaining blocks run y/x of the CURRENT chunk
// (midr -> outp). Independent buffers -> co-scheduled overlap.
// ---------------------------------------------------------------------------
template<int N, int NSEG, int PP, int TY, int NQ, int NCH, int CS>
__global__ void k_pipe(const float* __restrict__ lo,
                       const float* __restrict__ yh,
                       float* __restrict__ midw,
                       const float* __restrict__ midr,
                       float* __restrict__ outp,
                       int nzblk)
{
    extern __shared__ float sm[];
    constexpr int ITEMS = (N * N / 2) * NSEG;   // float2 z body
    constexpr int NTX   = (N - 3) / TY;
    constexpr int M     = 2 * N - 6;

    if ((int)blockIdx.x < nzblk) {
        int flat = blockIdx.x * TPB + threadIdx.x;
        int g = flat / ITEMS;
        if (g >= CS * 4) return;
        zpass2_dev<N, PP>(flat - g * ITEMS, g, lo, yh, midw);
    } else {
        int yxid  = blockIdx.x - nzblk;
        int tilex = yxid % NTX;
        int rest  = yxid / NTX;
        int oz    = rest % M;
        int slice = rest / M;
        kyx_dev<N, TY, NQ, NCH>(sm, threadIdx.x, tilex, oz, slice, midr, outp);
    }
}

extern "C" void kernel_launch(void* const* d_in, const int* in_sizes, int n_in,
                              void* d_out, int out_size)
{
    (void)in_sizes; (void)n_in; (void)out_size;

    const float* yl  = (const float*)d_in[0];  // (2,8,36,36,36)   16 slices
    const float* yh0 = (const float*)d_in[1];  // (2,8,7,66,66,66)
    const float* yh1 = (const float*)d_in[2];  // (2,8,7,36,36,36)
    float* out = (float*)d_out;                // (2,8,126,126,126)

    float *MIDA, *MIDB, *LL1;
    cudaGetSymbolAddress((void**)&MIDA, g_midA);
    cudaGetSymbolAddress((void**)&MIDB, g_midB);
    cudaGetSymbolAddress((void**)&LL1, g_LL1);

    // ---------------- Level 1: n=36 -> 66 (MID = 21.9 MB in buffer A) ------
    {
        constexpr int N = 36, M = 2 * N - 6;
        constexpr int ITEMS = (N * N / 4) * 3;       // NSEG=3, PP=11
        dim3 gz((ITEMS + TPB - 1) / TPB, 64);
        k_zpass<N, 3, 11><<<gz, TPB>>>(yl, yh1, MIDA);

        constexpr int TY = 11;                       // 33 = 3*11
        dim3 gyx((N - 3) / TY, M, 16);
        size_t sh = (size_t)(4 * (TY + 3) * N + 2 * (2 * TY) * N) * sizeof(float);
        k_yx<N, TY, 4, 11><<<gyx, TPB, sh>>>(MIDA, LL1);
    }

    // ---------------- Level 2: n=66 -> 126, pipelined chunks of 4 slices ----
    {
        constexpr int N = 66, M = 2 * N - 6;
        constexpr int CS = 4;
        constexpr int VOL  = N * N * N;
        constexpr int MVOL = M * M * M;
        constexpr int NSEG = 7, PP = 9;              // 63 = 7*9
        constexpr int TY = 9, NQ = 3, NCH = 21;
        constexpr int ITEMS = (N * N / 2) * NSEG;    // float2 body: 15246
        const int NZB  = (ITEMS * CS * 4 + TPB - 1) / TPB;   // 953
        const int NYXB = ((N - 3) / TY) * M * CS;            // 3528
        size_t sh = (size_t)(4 * (TY + 3) * N + 2 * (2 * TY) * N) * sizeof(float);

        float* bufs[2] = { MIDA, MIDB };

        for (int i = 0; i <= 4; i++) {
            const bool hasz  = (i < 4);
            const bool hasyx = (i > 0);
            const float* lo_c = LL1 + (hasz ? (size_t)i * CS * VOL : 0);
            const float* yh_c = yh0 + (hasz ? (size_t)i * CS * 7 * VOL : 0);
            float* midw = bufs[i & 1];
            const float* midr = bufs[(i + 1) & 1];
            float* out_c = out + (hasyx ? (size_t)(i - 1) * CS * MVOL : 0);
            int nzb = hasz ? NZB : 0;
            int nb  = nzb + (hasyx ? NYXB : 0);
            k_pipe<N, NSEG, PP, TY, NQ, NCH, CS><<<nb, TPB, sh>>>(
                lo_c, yh_c, midw, midr, out_c, nzb);
        }
    }
}

// round 13
// speedup vs baseline: 1.3493x; 1.3493x over previous
#include <cuda_runtime.h>

// ---------------------------------------------------------------------------
// 2-level 3D inverse DWT (db4, mode='zero'): segmented z streaming pass, then
// fused y+x. Exact-fit tiles, flat high-occupancy item maps, 3-pair rolling
// y-chunks, 4-pair float2 x-chunks, 32-bit addressing, float4 z-pass.
//
// Synthesis (L=8, conv_transpose stride 2, pad 6): out len M = 2n-6,
//   y[2p]   = sum_t x[p+t]*g[6-2t],  y[2p+1] = sum_t x[p+t]*g[7-2t]
// ---------------------------------------------------------------------------

#define G0_0 0.23037781330885523f
#define G0_1 0.7148465705525415f
#define G0_2 0.6308807679295904f
#define G0_3 (-0.02798376941698385f)
#define G0_4 (-0.18703481171888114f)
#define G0_5 0.030841381835986965f
#define G0_6 0.032883011666982945f
#define G0_7 (-0.010597401784997278f)

#define G1_0 (-0.010597401784997278f)
#define G1_1 (-0.032883011666982945f)
#define G1_2 0.030841381835986965f
#define G1_3 0.18703481171888114f
#define G1_4 (-0.02798376941698385f)
#define G1_5 (-0.6308807679295904f)
#define G1_6 0.7148465705525415f
#define G1_7 (-0.23037781330885523f)

__device__ __forceinline__ void sfb_pair(
    float l0, float l1, float l2, float l3,
    float h0, float h1, float h2, float h3,
    float& ye, float& yo)
{
    ye = fmaf(l0, G0_6,
         fmaf(l1, G0_4,
         fmaf(l2, G0_2,
         fmaf(l3, G0_0,
         fmaf(h0, G1_6,
         fmaf(h1, G1_4,
         fmaf(h2, G1_2,
              h3 * G1_0)))))));
    yo = fmaf(l0, G0_7,
         fmaf(l1, G0_5,
         fmaf(l2, G0_3,
         fmaf(l3, G0_1,
         fmaf(h0, G1_7,
         fmaf(h1, G1_5,
         fmaf(h2, G1_3,
              h3 * G1_1)))))));
}

__device__ __forceinline__ void sfb_pair2(
    float2 l0, float2 l1, float2 l2, float2 l3,
    float2 h0, float2 h1, float2 h2, float2 h3,
    float2& ye, float2& yo)
{
    sfb_pair(l0.x, l1.x, l2.x, l3.x, h0.x, h1.x, h2.x, h3.x, ye.x, yo.x);
    sfb_pair(l0.y, l1.y, l2.y, l3.y, h0.y, h1.y, h2.y, h3.y, ye.y, yo.y);
}

__device__ __forceinline__ void sfb_pair4(
    float4 l0, float4 l1, float4 l2, float4 l3,
    float4 h0, float4 h1, float4 h2, float4 h3,
    float4& ye, float4& yo)
{
    sfb_pair(l0.x, l1.x, l2.x, l3.x, h0.x, h1.x, h2.x, h3.x, ye.x, yo.x);
    sfb_pair(l0.y, l1.y, l2.y, l3.y, h0.y, h1.y, h2.y, h3.y, ye.y, yo.y);
    sfb_pair(l0.z, l1.z, l2.z, l3.z, h0.z, h1.z, h2.z, h3.z, ye.z, yo.z);
    sfb_pair(l0.w, l1.w, l2.w, l3.w, h0.w, h1.w, h2.w, h3.w, ye.w, yo.w);
}

// Scratch: z-pass output, level-2 max: 16 slices * 4 bands * 126 * 66*66
__device__ float g_mid[35126784];   // 140.5 MB
__device__ float g_LL1[4599936];    // 16 * 66^3 (18.4 MB)

// ---------------------------------------------------------------------------
// Kernel 1: z synthesis, SEGMENTED streaming lines, float4 over inner (y*x).
// 8 bands -> 4. Thread = (segment of PP pairs, float4 column). NSEG*PP = N-3.
// Output layout: [slice][b4][M_z][N^2].
// ---------------------------------------------------------------------------
template<int N, int NSEG, int PP>
__global__ void k_zpass(const float* __restrict__ lo_t,
                        const float* __restrict__ yh,
                        float* __restrict__ out)
{
    constexpr int N2  = N * N;
    constexpr int M   = 2 * N - 6;
    constexpr int S   = N2 / 4;          // float4 stride along z
    constexpr int VOL = N2 * N;
    constexpr int ITEMS = S * NSEG;

    int idx = blockIdx.x * blockDim.x + threadIdx.x;
    if (idx >= ITEMS) return;
    int i4  = idx % S;
    int seg = idx / S;
    int p0  = seg * PP;

    const int g = blockIdx.y;            // slice*4 + b4
    const int slice = g >> 2;
    const int b4 = g & 3;

    const float* lo_s = (b4 == 0) ? lo_t + slice * VOL
                                  : yh + (slice * 7 + (b4 - 1)) * VOL;
    const float* hi_s = yh + (slice * 7 + (b4 + 3)) * VOL;

    const float4* lp = (const float4*)lo_s + i4 + p0 * S;
    const float4* hp = (const float4*)hi_s + i4 + p0 * S;
    float4* op = (float4*)(out + g * M * N2) + i4 + 2 * p0 * S;

    float4 l0 = lp[0], l1 = lp[S], l2 = lp[2 * S];
    float4 h0 = hp[0], h1 = hp[S], h2 = hp[2 * S];
    lp += 3 * S; hp += 3 * S;

    #pragma unroll 3
    for (int p = 0; p < PP; p++) {
        float4 l3 = *lp, h3 = *hp;
        float4 ye, yo;
        sfb_pair4(l0, l1, l2, l3, h0, h1, h2, h3, ye, yo);
        op[0] = ye;
        op[S] = yo;
        l0 = l1; l1 = l2; l2 = l3;
        h0 = h1; h1 = h2; h2 = h3;
        lp += S; hp += S; op += 2 * S;
    }
}

// ---------------------------------------------------------------------------
// Kernel 2: fused y + x synthesis. 4 bands -> 1. Requires TY | (N-3); window
// (TY+3) rows always in range -> NO bounds checks on memory.
//   Block = (y-tile of TY pairs, oz, slice).
//   smem: s_in [4][TY+3][N], s_mid [2][2*TY][N]
//   y items: (j<2, q<NQ, x2<N/2), chunk of 3 pairs (2nd/3rd guarded by TY).
//   x items: (row<2*TY, c<NCH), chunk of 4 pairs via float2 LDS (guarded).
// ---------------------------------------------------------------------------
#define K2_TPB 256

template<int N, int TY, int NQ>
__global__ void k_yx(const float* __restrict__ in,
                     float* __restrict__ out)
{
    constexpr int N2   = N * N;
    constexpr int M    = 2 * N - 6;
    constexpr int NPX  = N - 3;
    constexpr int NH   = N / 2;
    constexpr int WINY = TY + 3;
    constexpr int ROWS = 2 * TY;
    constexpr int MN2  = M * N2;          // band stride in MID
    constexpr int MVOL = M * M * M;
    constexpr int NCH  = (NPX + 3) / 4;   // x-chunks of 4 pairs

    extern __shared__ float sm[];
    float* s_in  = sm;                  // [4][WINY][N]
    float* s_mid = sm + 4 * WINY * N;   // [2][ROWS][N]

    const int tid   = threadIdx.x;
    const int slice = blockIdx.z;
    const int oz    = blockIdx.y;
    const int py0   = blockIdx.x * TY;

    // ---- load 4 bands x WINY rows x N floats (float2, coalesced, no guards)
    {
        const float* base = in + (slice * 4 * M + oz) * N2 + py0 * N;
        constexpr int NLOAD = 4 * WINY * NH;
        constexpr int KL = (NLOAD + K2_TPB - 1) / K2_TPB;
        #pragma unroll
        for (int k = 0; k < KL; k++) {
            int idx = tid + k * K2_TPB;
            if (KL * K2_TPB == NLOAD || idx < NLOAD) {
                int b  = idx / (WINY * NH);
                int r  = idx - b * (WINY * NH);
                int iy = r / NH;
                int x2 = r - iy * NH;
                float2 v = *(const float2*)(base + b * MN2 + iy * N + 2 * x2);
                *(float2*)(s_in + (b * WINY + iy) * N + 2 * x2) = v;
            }
        }
    }
    __syncthreads();

    // ---- y synthesis: bands (j, j+2) -> s_mid[j]; chunk of 3 pairs, rolling
    {
        constexpr int YIT = 2 * NQ * NH;
        constexpr int KY = (YIT + K2_TPB - 1) / K2_TPB;
        #pragma unroll
        for (int k = 0; k < KY; k++) {
            int idx = tid + k * K2_TPB;
            if (KY * K2_TPB == YIT || idx < YIT) {
                int x2 = idx % NH;
                int rr = idx / NH;
                int q  = rr % NQ;
                int j  = rr / NQ;
                int p0 = 3 * q;
                const float* lp = s_in + (j * WINY + p0) * N + 2 * x2;
                const float* hp = lp + 2 * WINY * N;
                float2 l0 = *(const float2*)(lp);
                float2 l1 = *(const float2*)(lp + N);
                float2 l2 = *(const float2*)(lp + 2 * N);
                float2 l3 = *(const float2*)(lp + 3 * N);
                float2 h0 = *(const float2*)(hp);
                float2 h1 = *(const float2*)(hp + N);
                float2 h2 = *(const float2*)(hp + 2 * N);
                float2 h3 = *(const float2*)(hp + 3 * N);
                float* op = s_mid + (j * ROWS + 2 * p0) * N + 2 * x2;
                float2 ye, yo;
                sfb_pair2(l0, l1, l2, l3, h0, h1, h2, h3, ye, yo);
                *(float2*)(op)     = ye;
                *(float2*)(op + N) = yo;
                if (p0 + 1 < TY) {
                    float2 l4 = *(const float2*)(lp + 4 * N);
                    float2 h4 = *(const float2*)(hp + 4 * N);
                    sfb_pair2(l1, l2, l3, l4, h1, h2, h3, h4, ye, yo);
                    *(float2*)(op + 2 * N) = ye;
                    *(float2*)(op + 3 * N) = yo;
                    if (p0 + 2 < TY) {
                        float2 l5 = *(const float2*)(lp + 5 * N);
                        float2 h5 = *(const float2*)(hp + 5 * N);
                        sfb_pair2(l2, l3, l4, l5, h2, h3, h4, h5, ye, yo);
                        *(float2*)(op + 4 * N) = ye;
                        *(float2*)(op + 5 * N) = yo;
                    }
                }
            }
        }
    }
    __syncthreads();

    // ---- x synthesis: item = (row, chunk of 4 pairs), float2 LDS ----
    // p0 = 4c (even -> 8B aligned). Scalars needed: p0..p0+6 (full chunk).
    // Conditional tail loads keep every LDS in-range for partial chunks.
    {
        constexpr int XIT = ROWS * NCH;
        constexpr int KX = (XIT + K2_TPB - 1) / K2_TPB;
        float* oslab = out + slice * MVOL + (oz * M + 2 * py0) * M;
        #pragma unroll
        for (int k = 0; k < KX; k++) {
            int idx = tid + k * K2_TPB;
            if (KX * K2_TPB == XIT || idx < XIT) {
                int c   = idx % NCH;
                int row = idx / NCH;
                int p0  = 4 * c;
                const float2* lp2 = (const float2*)(s_mid + row * N + p0);
                const float2* hp2 = (const float2*)(s_mid + (ROWS + row) * N + p0);
                float2 A0 = lp2[0], A1 = lp2[1];
                float2 B0 = hp2[0], B1 = hp2[1];
                float2 A2 = make_float2(0.f, 0.f), B2 = A2;
                float2 A3 = A2, B3 = A2;
                bool has2 = (p0 + 1 < NPX);      // scalars p0+4, p0+5 needed
                bool has3 = (p0 + 4 <= NPX);     // scalars p0+6, p0+7 needed
                if (has2) { A2 = lp2[2]; B2 = hp2[2]; }
                if (has3) { A3 = lp2[3]; B3 = hp2[3]; }

                float a0 = A0.x, a1 = A0.y, a2 = A1.x, a3 = A1.y;
                float a4 = A2.x, a5 = A2.y, a6 = A3.x, a7 = A3.y;
                float b0 = B0.x, b1 = B0.y, b2 = B1.x, b3 = B1.y;
                float b4 = B2.x, b5 = B2.y, b6 = B3.x, b7 = B3.y;

                float* o = oslab + row * M + 2 * p0;
                float ye, yo;
                sfb_pair(a0, a1, a2, a3, b0, b1, b2, b3, ye, yo);
                *(float2*)(o) = make_float2(ye, yo);
                if (p0 + 1 < NPX) {
                    sfb_pair(a1, a2, a3, a4, b1, b2, b3, b4, ye, yo);
                    *(float2*)(o + 2) = make_float2(ye, yo);
                }
                if (p0 + 2 < NPX) {
                    sfb_pair(a2, a3, a4, a5, b2, b3, b4, b5, ye, yo);
                    *(float2*)(o + 4) = make_float2(ye, yo);
                }
                if (p0 + 3 < NPX) {
                    sfb_pair(a3, a4, a5, a6, b3, b4, b5, b6, ye, yo);
                    *(float2*)(o + 6) = make_float2(ye, yo);
                }
            }
        }
    }
}

extern "C" void kernel_launch(void* const* d_in, const int* in_sizes, int n_in,
                              void* d_out, int out_size)
{
    (void)in_sizes; (void)n_in; (void)out_size;

    const float* yl  = (const float*)d_in[0];  // (2,8,36,36,36)   16 slices
    const float* yh0 = (const float*)d_in[1];  // (2,8,7,66,66,66)
    const float* yh1 = (const float*)d_in[2];  // (2,8,7,36,36,36)
    float* out = (float*)d_out;                // (2,8,126,126,126)

    float *MID, *LL1;
    cudaGetSymbolAddress((void**)&MID, g_mid);
    cudaGetSymbolAddress((void**)&LL1, g_LL1);

    // ---------------- Level 1: n=36 -> 66 ----------------
    {
        constexpr int N = 36, M = 2 * N - 6;
        constexpr int ITEMS = (N * N / 4) * 3;       // NSEG=3, PP=11
        dim3 gz((ITEMS + 127) / 128, 64);
        k_zpass<N, 3, 11><<<gz, 128>>>(yl, yh1, MID);

        constexpr int TY = 11;                       // 33 = 3*11, NQ=4
        dim3 gyx((N - 3) / TY, M, 16);
        size_t sh = (size_t)(4 * (TY + 3) * N + 2 * (2 * TY) * N) * sizeof(float);
        k_yx<N, TY, 4><<<gyx, K2_TPB, sh>>>(MID, LL1);
    }

    // ---------------- Level 2: n=66 -> 126 ----------------
    {
        constexpr int N = 66, M = 2 * N - 6;
        constexpr int ITEMS = (N * N / 4) * 7;       // NSEG=7, PP=9 (R7-proven)
        dim3 gz((ITEMS + 127) / 128, 64);
        k_zpass<N, 7, 9><<<gz, 128>>>(LL1, yh0, MID);

        constexpr int TY = 9;                        // 63 = 7*9, NQ=3
        dim3 gyx((N - 3) / TY, M, 16);
        size_t sh = (size_t)(4 * (TY + 3) * N + 2 * (2 * TY) * N) * sizeof(float);
        k_yx<N, TY, 3><<<gyx, K2_TPB, sh>>>(MID, out);
    }
}

// round 14
// speedup vs baseline: 1.6936x; 1.2552x over previous
#include <cuda_runtime.h>

// ---------------------------------------------------------------------------
// 2-level 3D inverse DWT (db4, mode='zero'): segmented z streaming pass, then
// fused y+x. The y-stage reads GLOBAL directly (coalesced float2) - no s_in
// staging buffer, no load stage, one sync. x-stage: scalar rolling 3-pair
// chunks (measured optimum). Exact-fit tiles, float4 z-pass, 32-bit indexing.
//
// Synthesis (L=8, conv_transpose stride 2, pad 6): out len M = 2n-6,
//   y[2p]   = sum_t x[p+t]*g[6-2t],  y[2p+1] = sum_t x[p+t]*g[7-2t]
// ---------------------------------------------------------------------------

#define G0_0 0.23037781330885523f
#define G0_1 0.7148465705525415f
#define G0_2 0.6308807679295904f
#define G0_3 (-0.02798376941698385f)
#define G0_4 (-0.18703481171888114f)
#define G0_5 0.030841381835986965f
#define G0_6 0.032883011666982945f
#define G0_7 (-0.010597401784997278f)

#define G1_0 (-0.010597401784997278f)
#define G1_1 (-0.032883011666982945f)
#define G1_2 0.030841381835986965f
#define G1_3 0.18703481171888114f
#define G1_4 (-0.02798376941698385f)
#define G1_5 (-0.6308807679295904f)
#define G1_6 0.7148465705525415f
#define G1_7 (-0.23037781330885523f)

__device__ __forceinline__ void sfb_pair(
    float l0, float l1, float l2, float l3,
    float h0, float h1, float h2, float h3,
    float& ye, float& yo)
{
    ye = fmaf(l0, G0_6,
         fmaf(l1, G0_4,
         fmaf(l2, G0_2,
         fmaf(l3, G0_0,
         fmaf(h0, G1_6,
         fmaf(h1, G1_4,
         fmaf(h2, G1_2,
              h3 * G1_0)))))));
    yo = fmaf(l0, G0_7,
         fmaf(l1, G0_5,
         fmaf(l2, G0_3,
         fmaf(l3, G0_1,
         fmaf(h0, G1_7,
         fmaf(h1, G1_5,
         fmaf(h2, G1_3,
              h3 * G1_1)))))));
}

__device__ __forceinline__ void sfb_pair2(
    float2 l0, float2 l1, float2 l2, float2 l3,
    float2 h0, float2 h1, float2 h2, float2 h3,
    float2& ye, float2& yo)
{
    sfb_pair(l0.x, l1.x, l2.x, l3.x, h0.x, h1.x, h2.x, h3.x, ye.x, yo.x);
    sfb_pair(l0.y, l1.y, l2.y, l3.y, h0.y, h1.y, h2.y, h3.y, ye.y, yo.y);
}

__device__ __forceinline__ void sfb_pair4(
    float4 l0, float4 l1, float4 l2, float4 l3,
    float4 h0, float4 h1, float4 h2, float4 h3,
    float4& ye, float4& yo)
{
    sfb_pair(l0.x, l1.x, l2.x, l3.x, h0.x, h1.x, h2.x, h3.x, ye.x, yo.x);
    sfb_pair(l0.y, l1.y, l2.y, l3.y, h0.y, h1.y, h2.y, h3.y, ye.y, yo.y);
    sfb_pair(l0.z, l1.z, l2.z, l3.z, h0.z, h1.z, h2.z, h3.z, ye.z, yo.z);
    sfb_pair(l0.w, l1.w, l2.w, l3.w, h0.w, h1.w, h2.w, h3.w, ye.w, yo.w);
}

// Scratch: z-pass output, level-2 max: 16 slices * 4 bands * 126 * 66*66
__device__ float g_mid[35126784];   // 140.5 MB
__device__ float g_LL1[4599936];    // 16 * 66^3 (18.4 MB)

// ---------------------------------------------------------------------------
// Kernel 1: z synthesis, SEGMENTED streaming lines, float4 over inner (y*x).
// 8 bands -> 4. Thread = (segment of PP pairs, float4 column). NSEG*PP = N-3.
// Output layout: [slice][b4][M_z][N^2].
// ---------------------------------------------------------------------------
template<int N, int NSEG, int PP>
__global__ void k_zpass(const float* __restrict__ lo_t,
                        const float* __restrict__ yh,
                        float* __restrict__ out)
{
    constexpr int N2  = N * N;
    constexpr int M   = 2 * N - 6;
    constexpr int S   = N2 / 4;          // float4 stride along z
    constexpr int VOL = N2 * N;
    constexpr int ITEMS = S * NSEG;

    int idx = blockIdx.x * blockDim.x + threadIdx.x;
    if (idx >= ITEMS) return;
    int i4  = idx % S;
    int seg = idx / S;
    int p0  = seg * PP;

    const int g = blockIdx.y;            // slice*4 + b4
    const int slice = g >> 2;
    const int b4 = g & 3;

    const float* lo_s = (b4 == 0) ? lo_t + slice * VOL
                                  : yh + (slice * 7 + (b4 - 1)) * VOL;
    const float* hi_s = yh + (slice * 7 + (b4 + 3)) * VOL;

    const float4* lp = (const float4*)lo_s + i4 + p0 * S;
    const float4* hp = (const float4*)hi_s + i4 + p0 * S;
    float4* op = (float4*)(out + g * M * N2) + i4 + 2 * p0 * S;

    float4 l0 = lp[0], l1 = lp[S], l2 = lp[2 * S];
    float4 h0 = hp[0], h1 = hp[S], h2 = hp[2 * S];
    lp += 3 * S; hp += 3 * S;

    #pragma unroll 3
    for (int p = 0; p < PP; p++) {
        float4 l3 = *lp, h3 = *hp;
        float4 ye, yo;
        sfb_pair4(l0, l1, l2, l3, h0, h1, h2, h3, ye, yo);
        op[0] = ye;
        op[S] = yo;
        l0 = l1; l1 = l2; l2 = l3;
        h0 = h1; h1 = h2; h2 = h3;
        lp += S; hp += S; op += 2 * S;
    }
}

// ---------------------------------------------------------------------------
// Kernel 2: fused y + x synthesis. 4 bands -> 1. Requires TY | (N-3); the
// y-window (TY+3 rows) is always in range -> NO bounds checks on memory.
//   Block = (y-tile of TY pairs, oz, slice).  smem: s_mid [2][2*TY][N] ONLY.
//   y items: (j<2, q<NQ, x2<N/2), 3-pair rolling chunk, LOADS FROM GLOBAL
//            (adjacent x2 -> contiguous float2: fully coalesced LDG.64).
//   x items: (row<2*TY, c<NCH), exactly 3 pairs rolling, scalar LDS.
// ---------------------------------------------------------------------------
#define K2_TPB 256

template<int N, int TY, int NQ, int NCH>
__global__ void k_yx(const float* __restrict__ in,
                     float* __restrict__ out)
{
    constexpr int N2   = N * N;
    constexpr int M    = 2 * N - 6;
    constexpr int NH   = N / 2;
    constexpr int ROWS = 2 * TY;
    constexpr int MN2  = M * N2;          // band stride in MID
    constexpr int MVOL = M * M * M;

    extern __shared__ float sm[];
    float* s_mid = sm;                  // [2][ROWS][N]

    const int tid   = threadIdx.x;
    const int slice = blockIdx.z;
    const int oz    = blockIdx.y;
    const int py0   = blockIdx.x * TY;

    // ---- y synthesis from GLOBAL: bands (j, j+2) -> s_mid[j] ----
    {
        constexpr int YIT = 2 * NQ * NH;
        constexpr int KY = (YIT + K2_TPB - 1) / K2_TPB;
        const float* base = in + (slice * 4 * M + oz) * N2 + py0 * N;
        #pragma unroll
        for (int k = 0; k < KY; k++) {
            int idx = tid + k * K2_TPB;
            if (KY * K2_TPB == YIT || idx < YIT) {
                int x2 = idx % NH;
                int rr = idx / NH;
                int q  = rr % NQ;
                int j  = rr / NQ;
                int p0 = 3 * q;
                const float* lp = base + j * MN2 + p0 * N + 2 * x2;
                const float* hp = lp + 2 * MN2;
                float2 l0 = *(const float2*)(lp);
                float2 l1 = *(const float2*)(lp + N);
                float2 l2 = *(const float2*)(lp + 2 * N);
                float2 l3 = *(const float2*)(lp + 3 * N);
                float2 h0 = *(const float2*)(hp);
                float2 h1 = *(const float2*)(hp + N);
                float2 h2 = *(const float2*)(hp + 2 * N);
                float2 h3 = *(const float2*)(hp + 3 * N);
                float* op = s_mid + (j * ROWS + 2 * p0) * N + 2 * x2;
                float2 ye, yo;
                sfb_pair2(l0, l1, l2, l3, h0, h1, h2, h3, ye, yo);
                *(float2*)(op)     = ye;
                *(float2*)(op + N) = yo;
                if (p0 + 1 < TY) {
                    float2 l4 = *(const float2*)(lp + 4 * N);
                    float2 h4 = *(const float2*)(hp + 4 * N);
                    sfb_pair2(l1, l2, l3, l4, h1, h2, h3, h4, ye, yo);
                    *(float2*)(op + 2 * N) = ye;
                    *(float2*)(op + 3 * N) = yo;
                    if (p0 + 2 < TY) {
                        float2 l5 = *(const float2*)(lp + 5 * N);
                        float2 h5 = *(const float2*)(hp + 5 * N);
                        sfb_pair2(l2, l3, l4, l5, h2, h3, h4, h5, ye, yo);
                        *(float2*)(op + 4 * N) = ye;
                        *(float2*)(op + 5 * N) = yo;
                    }
                }
            }
        }
    }
    __syncthreads();

    // ---- x synthesis: item = (row, chunk of 3 pairs), rolling, to global ----
    {
        constexpr int XIT = ROWS * NCH;
        constexpr int KX = (XIT + K2_TPB - 1) / K2_TPB;
        float* oslab = out + slice * MVOL + (oz * M + 2 * py0) * M;
        #pragma unroll
        for (int k = 0; k < KX; k++) {
            int idx = tid + k * K2_TPB;
            if (KX * K2_TPB == XIT || idx < XIT) {
                int c   = idx % NCH;
                int row = idx / NCH;
                int p0  = 3 * c;
                const float* lp = s_mid + row * N + p0;
                const float* hp = lp + ROWS * N;
                float l0 = lp[0], l1 = lp[1], l2 = lp[2];
                float h0 = hp[0], h1 = hp[1], h2 = hp[2];
                float* o = oslab + row * M + 2 * p0;
                #pragma unroll
                for (int s = 0; s < 3; s++) {
                    float l3 = lp[3 + s], h3 = hp[3 + s];
                    float ye, yo;
                    sfb_pair(l0, l1, l2, l3, h0, h1, h2, h3, ye, yo);
                    *(float2*)(o + 2 * s) = make_float2(ye, yo);
                    l0 = l1; l1 = l2; l2 = l3;
                    h0 = h1; h1 = h2; h2 = h3;
                }
            }
        }
    }
}

extern "C" void kernel_launch(void* const* d_in, const int* in_sizes, int n_in,
                              void* d_out, int out_size)
{
    (void)in_sizes; (void)n_in; (void)out_size;

    const float* yl  = (const float*)d_in[0];  // (2,8,36,36,36)   16 slices
    const float* yh0 = (const float*)d_in[1];  // (2,8,7,66,66,66)
    const float* yh1 = (const float*)d_in[2];  // (2,8,7,36,36,36)
    float* out = (float*)d_out;                // (2,8,126,126,126)

    float *MID, *LL1;
    cudaGetSymbolAddress((void**)&MID, g_mid);
    cudaGetSymbolAddress((void**)&LL1, g_LL1);

    // ---------------- Level 1: n=36 -> 66 ----------------
    {
        constexpr int N = 36, M = 2 * N - 6;
        constexpr int ITEMS = (N * N / 4) * 3;       // NSEG=3, PP=11
        dim3 gz((ITEMS + 127) / 128, 64);
        k_zpass<N, 3, 11><<<gz, 128>>>(yl, yh1, MID);

        constexpr int TY = 11;                       // 33 = 3*11, NQ=4, NCH=11
        dim3 gyx((N - 3) / TY, M, 16);
        size_t sh = (size_t)(2 * (2 * TY) * N) * sizeof(float);
        k_yx<N, TY, 4, 11><<<gyx, K2_TPB, sh>>>(MID, LL1);
    }

    // ---------------- Level 2: n=66 -> 126 ----------------
    {
        constexpr int N = 66, M = 2 * N - 6;
        constexpr int ITEMS = (N * N / 4) * 7;       // NSEG=7, PP=9 (R7-proven)
        dim3 gz((ITEMS + 127) / 128, 64);
        k_zpass<N, 7, 9><<<gz, 128>>>(LL1, yh0, MID);

        constexpr int TY = 9;                        // 63 = 7*9, NQ=3, NCH=21
        dim3 gyx((N - 3) / TY, M, 16);
        size_t sh = (size_t)(2 * (2 * TY) * N) * sizeof(float);
        k_yx<N, TY, 3, 21><<<gyx, K2_TPB, sh>>>(MID, out);
    }
}